// round 1
// baseline (speedup 1.0000x reference)
#include <cuda_runtime.h>

// ---------------------------------------------------------------------------
// VectorQuantizer forward, fused.
//   z:   [8, 32, 32, 32] fp32 (NCHW)   -> tokens N=8192, C=32
//   emb: [8192, 32] fp32               -> V=8192 codes
// Outputs (concatenated): out tensor [8,32,32,32] (65536), vq_loss, commit_loss
//
// Math collapses used (forward values only):
//   logits == S == zfn @ en^T            (stop_gradient irrelevant in fwd)
//   argmin d == argmin over v of (esq_v - 2*S[n,v])   (zsq_n constant per row)
//   z_q == en[idx]                        (l2norm commutes with row gather)
//   out == z_q in NCHW                    (straight-through fwd value)
//   commit = BETA * mean_n( logsumexp_v S[n,:] - S[n,idx_n] )
//   vq     = mean_{n,c} (en[idx_n][c] - zfn[n][c])^2
// ---------------------------------------------------------------------------

#define N_TOK 8192
#define V_CODES 8192
#define C_DIM 32
#define VS 8                 // vocab splits (grid.y)
#define VPB (V_CODES / VS)   // 1024 codes per block
#define TILE_V 64            // codes per smem tile
#define TPB 128              // threads per block (main kernel)
#define TOKB 256             // tokens per block (2 per thread)
#define L2EPS 1e-12f

typedef unsigned long long u64;

// ------------------------- device scratch (no allocs allowed) ---------------
__device__ float g_en[V_CODES * C_DIM];     // l2-normalized codebook
__device__ float g_esq[V_CODES];            // sum(en*en) per code
__device__ float g_zfn[N_TOK * C_DIM];      // l2-normalized tokens, row-major
__device__ float g_pd[VS * N_TOK];          // partial best distance
__device__ int   g_pi[VS * N_TOK];          // partial best index
__device__ float g_pbs[VS * N_TOK];         // dot at partial best
__device__ float g_pm[VS * N_TOK];          // partial running max (softmax)
__device__ float g_ps[VS * N_TOK];          // partial scaled exp-sum
__device__ float g_blk[32][2];              // per-block loss partials

// ------------------------- packed f32x2 helpers -----------------------------
__device__ __forceinline__ void fma2(u64& d, u64 a, u64 b) {
    asm("fma.rn.f32x2 %0, %1, %2, %0;" : "+l"(d) : "l"(a), "l"(b));
}
__device__ __forceinline__ u64 add2(u64 a, u64 b) {
    u64 r;
    asm("add.rn.f32x2 %0, %1, %2;" : "=l"(r) : "l"(a), "l"(b));
    return r;
}
__device__ __forceinline__ float f2sum(u64 a) {
    return __uint_as_float((unsigned)a) + __uint_as_float((unsigned)(a >> 32));
}

// ------------------------- kernel 1: normalize codebook ---------------------
__global__ void prep_emb(const float* __restrict__ emb) {
    int r = blockIdx.x * blockDim.x + threadIdx.x;
    if (r >= V_CODES) return;
    const float4* src = (const float4*)(emb + r * C_DIM);
    float4 v[8];
    float ss = 0.f;
#pragma unroll
    for (int i = 0; i < 8; i++) {
        v[i] = src[i];
        ss += v[i].x * v[i].x + v[i].y * v[i].y + v[i].z * v[i].z + v[i].w * v[i].w;
    }
    float rcp = 1.0f / fmaxf(sqrtf(ss), L2EPS);
    float es = 0.f;
    float4* dst = (float4*)(g_en + r * C_DIM);
#pragma unroll
    for (int i = 0; i < 8; i++) {
        v[i].x *= rcp; v[i].y *= rcp; v[i].z *= rcp; v[i].w *= rcp;
        es += v[i].x * v[i].x + v[i].y * v[i].y + v[i].z * v[i].z + v[i].w * v[i].w;
        dst[i] = v[i];
    }
    g_esq[r] = es;
}

// ------------------------- kernel 2: transpose+normalize z ------------------
__global__ void prep_z(const float* __restrict__ z) {
    int n = blockIdx.x * blockDim.x + threadIdx.x;
    if (n >= N_TOK) return;
    int b = n >> 10, hw = n & 1023;
    const float* zp = z + b * (C_DIM * 1024) + hw;
    float val[C_DIM];
    float ss = 0.f;
#pragma unroll
    for (int c = 0; c < C_DIM; c++) {
        val[c] = zp[c * 1024];           // stride H*W=1024; coalesced across lanes
        ss += val[c] * val[c];
    }
    float rcp = 1.0f / fmaxf(sqrtf(ss), L2EPS);
    float4* dst = (float4*)(g_zfn + n * C_DIM);
#pragma unroll
    for (int i = 0; i < 8; i++) {
        dst[i] = make_float4(val[4 * i] * rcp, val[4 * i + 1] * rcp,
                             val[4 * i + 2] * rcp, val[4 * i + 3] * rcp);
    }
}

// ------------------------- kernel 3: fused similarity scan ------------------
// grid = (N_TOK/TOKB, VS). Each block: 256 tokens x 1024 codes.
// Each thread: 2 tokens in registers (packed f32x2), streams code tiles
// from smem (LDS.128 broadcast), keeps argmin-d + online logsumexp.
__global__ __launch_bounds__(TPB) void vq_main() {
    __shared__ float sc[TILE_V * C_DIM];
    __shared__ float ssq[TILE_V];
    int tid = threadIdx.x;
    int tok0 = blockIdx.x * TOKB + tid;
    int tok1 = tok0 + TPB;
    int vbase = blockIdx.y * VPB;

    u64 zz0[16], zz1[16];
    {
        const u64* p0 = (const u64*)(g_zfn + tok0 * C_DIM);
        const u64* p1 = (const u64*)(g_zfn + tok1 * C_DIM);
#pragma unroll
        for (int k = 0; k < 16; k++) { zz0[k] = p0[k]; zz1[k] = p1[k]; }
    }

    float bestd0 = 3.4e38f, bestd1 = 3.4e38f;
    int bi0 = 0, bi1 = 0;
    float bs0 = 0.f, bs1 = 0.f;
    float m0 = -1e30f, m1 = -1e30f, s0 = 0.f, s1 = 0.f;

    for (int t = 0; t < VPB / TILE_V; t++) {
        int v0 = vbase + t * TILE_V;
        // cooperative tile load: 64 codes * 32 floats = 512 float4
        {
            const float4* src = (const float4*)(g_en + v0 * C_DIM);
            float4* dst = (float4*)sc;
#pragma unroll
            for (int i = 0; i < 4; i++) dst[tid + i * TPB] = src[tid + i * TPB];
            if (tid < TILE_V) ssq[tid] = g_esq[v0 + tid];
        }
        __syncthreads();

#pragma unroll 2
        for (int v = 0; v < TILE_V; v++) {
            const ulonglong2* e = (const ulonglong2*)(sc + v * C_DIM);
            ulonglong2 ev[8];
#pragma unroll
            for (int k = 0; k < 8; k++) ev[k] = e[k];   // 8x LDS.128 broadcast

            u64 a00 = 0ull, a01 = 0ull, a10 = 0ull, a11 = 0ull;
#pragma unroll
            for (int k = 0; k < 8; k++) {
                fma2(a00, zz0[2 * k],     ev[k].x);
                fma2(a01, zz0[2 * k + 1], ev[k].y);
                fma2(a10, zz1[2 * k],     ev[k].x);
                fma2(a11, zz1[2 * k + 1], ev[k].y);
            }
            float dot0 = f2sum(add2(a00, a01));
            float dot1 = f2sum(add2(a10, a11));
            float sq = ssq[v];
            float d0 = fmaf(-2.f, dot0, sq);
            float d1 = fmaf(-2.f, dot1, sq);
            if (d0 < bestd0) { bestd0 = d0; bi0 = v0 + v; bs0 = dot0; }
            if (d1 < bestd1) { bestd1 = d1; bi1 = v0 + v; bs1 = dot1; }
            // branchless online logsumexp
            float nm0 = fmaxf(m0, dot0);
            s0 = fmaf(s0, __expf(m0 - nm0), __expf(dot0 - nm0));
            m0 = nm0;
            float nm1 = fmaxf(m1, dot1);
            s1 = fmaf(s1, __expf(m1 - nm1), __expf(dot1 - nm1));
            m1 = nm1;
        }
        __syncthreads();
    }

    int o0 = blockIdx.y * N_TOK + tok0;
    int o1 = blockIdx.y * N_TOK + tok1;
    g_pd[o0] = bestd0; g_pi[o0] = bi0; g_pbs[o0] = bs0; g_pm[o0] = m0; g_ps[o0] = s0;
    g_pd[o1] = bestd1; g_pi[o1] = bi1; g_pbs[o1] = bs1; g_pm[o1] = m1; g_ps[o1] = s1;
}

// ------------------------- kernel 4: merge splits, gather, losses -----------
__global__ void vq_combine(float* __restrict__ out) {
    __shared__ float sv[256], scm[256];
    int n = blockIdx.x * 256 + threadIdx.x;

    float bestd = 3.4e38f; int bi = 0; float bs = 0.f;
    float m = -1e30f;
#pragma unroll
    for (int sp = 0; sp < VS; sp++) {
        float d = g_pd[sp * N_TOK + n];
        if (d < bestd) { bestd = d; bi = g_pi[sp * N_TOK + n]; bs = g_pbs[sp * N_TOK + n]; }
        m = fmaxf(m, g_pm[sp * N_TOK + n]);
    }
    float S = 0.f;
#pragma unroll
    for (int sp = 0; sp < VS; sp++)
        S += g_ps[sp * N_TOK + n] * __expf(g_pm[sp * N_TOK + n] - m);
    float lse = m + __logf(S);
    float commit = lse - bs;

    const float* e = g_en + bi * C_DIM;
    const float* zr = g_zfn + n * C_DIM;
    int b = n >> 10, hw = n & 1023;
    float* op = out + b * (C_DIM * 1024) + hw;
    float vq = 0.f;
#pragma unroll
    for (int c = 0; c < C_DIM; c++) {
        float ev = e[c];
        float df = ev - zr[c];
        vq = fmaf(df, df, vq);
        op[c * 1024] = ev;       // NCHW scatter, coalesced across lanes per c
    }

    sv[threadIdx.x] = vq;
    scm[threadIdx.x] = commit;
    __syncthreads();
    for (int st = 128; st > 0; st >>= 1) {
        if (threadIdx.x < st) {
            sv[threadIdx.x] += sv[threadIdx.x + st];
            scm[threadIdx.x] += scm[threadIdx.x + st];
        }
        __syncthreads();
    }
    if (threadIdx.x == 0) {
        g_blk[blockIdx.x][0] = sv[0];
        g_blk[blockIdx.x][1] = scm[0];
    }
}

// ------------------------- kernel 5: final scalar reduce --------------------
__global__ void vq_final(float* __restrict__ out, int out_size) {
    float v = 0.f, c = 0.f;
    for (int i = 0; i < 32; i++) { v += g_blk[i][0]; c += g_blk[i][1]; }
    out[out_size - 2] = v / (float)(N_TOK * C_DIM);          // vq_loss
    out[out_size - 1] = 0.25f * (c / (float)N_TOK);          // commit_loss (BETA)
}

// ---------------------------------------------------------------------------
extern "C" void kernel_launch(void* const* d_in, const int* in_sizes, int n_in,
                              void* d_out, int out_size) {
    const float* z = (const float*)d_in[0];
    const float* emb = (const float*)d_in[1];
    // metadata order should be (z, emb); guard by element counts anyway.
    if (n_in >= 2 && in_sizes[0] == V_CODES * C_DIM && in_sizes[1] == N_TOK * 8) {
        const float* t = z; z = emb; emb = t;
    }

    prep_emb<<<V_CODES / 256, 256>>>(emb);
    prep_z<<<N_TOK / 256, 256>>>(z);
    dim3 grid(N_TOK / TOKB, VS);
    vq_main<<<grid, TPB>>>();
    vq_combine<<<N_TOK / 256, 256>>>((float*)d_out);
    vq_final<<<1, 1>>>((float*)d_out, out_size);
}

// round 2
// speedup vs baseline: 1.2123x; 1.2123x over previous
#include <cuda_runtime.h>

// ---------------------------------------------------------------------------
// VectorQuantizer forward, fused.  N=8192 tokens x V=8192 codes x C=32.
// Forward-value collapses:
//   logits == S == zfn @ en^T ; argmin d == argmin_v (esq_v - 2 S[n,v])
//   z_q == en[idx] ; out == z_q (straight-through)
//   commit = BETA * mean_n( log(sum_v exp(S[n,v])) - S[n,idx_n] )
//   vq     = mean (en[idx]-zfn)^2
// dot in [-1,1] (normalized operands) -> no-max logsumexp is safe.
// Scale by log2e folded into esq so EX2 needs no per-element rescale; argmin
// ordering preserved (positive scale).
// ---------------------------------------------------------------------------

#define N_TOK 8192
#define V_CODES 8192
#define C_DIM 32
#define VS 16
#define VPB (V_CODES / VS)      // 512 codes per block
#define TILE_V 64
#define TPB 256
#define TOKB 512                // 2 tokens per thread
#define L2EPS 1e-12f
#define L2E 1.4426950408889634f
#define LN2 0.6931471805599453f

typedef unsigned long long u64;
typedef unsigned int u32;

// ------------------------- device scratch ----------------------------------
__device__ float g_en[V_CODES * C_DIM];     // l2-normalized codebook
__device__ u64   g_esqp[V_CODES];           // (esq*log2e, esq*log2e) packed
__device__ float g_zfn[N_TOK * C_DIM];      // l2-normalized tokens
__device__ float g_pd[N_TOK * VS];          // partial best (scaled) distance
__device__ int   g_pi[N_TOK * VS];          // partial best index
__device__ float g_ps[N_TOK * VS];          // partial exp-sum
__device__ float g_blk[64][2];              // per-block loss partials
__device__ int   g_cnt;                     // combine completion counter

// ------------------------- packed f32x2 helpers ----------------------------
__device__ __forceinline__ void fma2(u64& d, u64 a, u64 b) {
    asm("fma.rn.f32x2 %0, %1, %2, %0;" : "+l"(d) : "l"(a), "l"(b));
}
__device__ __forceinline__ u64 fma2c(u64 a, u64 b, u64 c) {
    u64 r; asm("fma.rn.f32x2 %0, %1, %2, %3;" : "=l"(r) : "l"(a), "l"(b), "l"(c));
    return r;
}
__device__ __forceinline__ u64 mul2(u64 a, u64 b) {
    u64 r; asm("mul.rn.f32x2 %0, %1, %2;" : "=l"(r) : "l"(a), "l"(b));
    return r;
}
__device__ __forceinline__ u64 add2(u64 a, u64 b) {
    u64 r; asm("add.rn.f32x2 %0, %1, %2;" : "=l"(r) : "l"(a), "l"(b));
    return r;
}
__device__ __forceinline__ u64 pack2(u32 lo, u32 hi) {
    u64 r; asm("mov.b64 %0, {%1,%2};" : "=l"(r) : "r"(lo), "r"(hi));
    return r;
}
__device__ __forceinline__ void unpack2(u64 v, u32& lo, u32& hi) {
    asm("mov.b64 {%0,%1}, %2;" : "=r"(lo), "=r"(hi) : "l"(v));
}
__device__ __forceinline__ float ex2f(float x) {
    float r; asm("ex2.approx.f32 %0, %1;" : "=f"(r) : "f"(x));
    return r;
}
__device__ __forceinline__ float lg2f(float x) {
    float r; asm("lg2.approx.f32 %0, %1;" : "=f"(r) : "f"(x));
    return r;
}

// ------------------------- kernel 1: prep (emb + z) ------------------------
__global__ void prep(const float* __restrict__ z, const float* __restrict__ emb) {
    int tid = threadIdx.x;
    if (blockIdx.x < 32) {
        int r = blockIdx.x * 256 + tid;
        const float4* src = (const float4*)(emb + r * C_DIM);
        float4 v[8];
        float ss = 0.f;
#pragma unroll
        for (int i = 0; i < 8; i++) {
            v[i] = src[i];
            ss += v[i].x * v[i].x + v[i].y * v[i].y + v[i].z * v[i].z + v[i].w * v[i].w;
        }
        float rcp = 1.0f / fmaxf(sqrtf(ss), L2EPS);
        float es = 0.f;
        float4* dst = (float4*)(g_en + r * C_DIM);
#pragma unroll
        for (int i = 0; i < 8; i++) {
            v[i].x *= rcp; v[i].y *= rcp; v[i].z *= rcp; v[i].w *= rcp;
            es += v[i].x * v[i].x + v[i].y * v[i].y + v[i].z * v[i].z + v[i].w * v[i].w;
            dst[i] = v[i];
        }
        u32 eb = __float_as_uint(es * L2E);
        g_esqp[r] = pack2(eb, eb);
    } else {
        int n = (blockIdx.x - 32) * 256 + tid;
        int b = n >> 10, hw = n & 1023;
        const float* zp = z + b * (C_DIM * 1024) + hw;
        float val[C_DIM];
        float ss = 0.f;
#pragma unroll
        for (int c = 0; c < C_DIM; c++) {
            val[c] = zp[c * 1024];
            ss += val[c] * val[c];
        }
        float rcp = 1.0f / fmaxf(sqrtf(ss), L2EPS);
        float4* dst = (float4*)(g_zfn + n * C_DIM);
#pragma unroll
        for (int i = 0; i < 8; i++) {
            dst[i] = make_float4(val[4 * i] * rcp, val[4 * i + 1] * rcp,
                                 val[4 * i + 2] * rcp, val[4 * i + 3] * rcp);
        }
    }
}

// ------------------------- kernel 2: fused similarity scan -----------------
// grid = (16, VS). Block: 512 tokens (2/thread) x 512 codes.
__global__ __launch_bounds__(TPB, 2) void vq_main() {
    __shared__ float sc[TILE_V * C_DIM];
    __shared__ u64 ssqp[TILE_V];
    int tid = threadIdx.x;
    int tok0 = blockIdx.x * TOKB + tid;
    int tok1 = tok0 + TPB;
    int vbase = blockIdx.y * VPB;

    u64 zz0[16], zz1[16];
    {
        const u64* p0 = (const u64*)(g_zfn + tok0 * C_DIM);
        const u64* p1 = (const u64*)(g_zfn + tok1 * C_DIM);
#pragma unroll
        for (int k = 0; k < 16; k++) { zz0[k] = p0[k]; zz1[k] = p1[k]; }
    }

    const u32 l2eb = __float_as_uint(L2E);
    const u32 n2b  = __float_as_uint(-2.0f);
    const u64 PL2E = pack2(l2eb, l2eb);
    const u64 PN2  = pack2(n2b, n2b);

    float bestd0 = 3.4e38f, bestd1 = 3.4e38f;
    int bi0 = 0, bi1 = 0;
    float s0 = 0.f, s1 = 0.f;

    for (int t = 0; t < VPB / TILE_V; t++) {
        int v0 = vbase + t * TILE_V;
        {
            const float4* src = (const float4*)(g_en + v0 * C_DIM);
            float4* dst = (float4*)sc;
            dst[tid] = src[tid];
            dst[tid + TPB] = src[tid + TPB];
            if (tid < TILE_V) ssqp[tid] = g_esqp[v0 + tid];
        }
        __syncthreads();

#pragma unroll 4
        for (int v = 0; v < TILE_V; v++) {
            const ulonglong2* e = (const ulonglong2*)(sc + v * C_DIM);
            ulonglong2 ev[8];
#pragma unroll
            for (int k = 0; k < 8; k++) ev[k] = e[k];   // 8x LDS.128 broadcast

            u64 a00 = mul2(zz0[0], ev[0].x);
            u64 a01 = mul2(zz0[1], ev[0].y);
            u64 a10 = mul2(zz1[0], ev[0].x);
            u64 a11 = mul2(zz1[1], ev[0].y);
#pragma unroll
            for (int k = 1; k < 8; k++) {
                fma2(a00, zz0[2 * k],     ev[k].x);
                fma2(a01, zz0[2 * k + 1], ev[k].y);
                fma2(a10, zz1[2 * k],     ev[k].x);
                fma2(a11, zz1[2 * k + 1], ev[k].y);
            }
            u64 r0 = add2(a00, a01);
            u64 r1 = add2(a10, a11);
            u32 r0l, r0h, r1l, r1h;
            unpack2(r0, r0l, r0h);
            unpack2(r1, r1l, r1h);
            u64 dd = add2(pack2(r0l, r1l), pack2(r0h, r1h)); // (dot0, dot1)
            u64 uu = mul2(dd, PL2E);                         // log2e * dot
            u64 dv = fma2c(uu, PN2, ssqp[v]);                // (d0, d1), scaled dist
            u32 d0b, d1b, u0b, u1b;
            unpack2(dv, d0b, d1b);
            unpack2(uu, u0b, u1b);
            float d0 = __uint_as_float(d0b), d1 = __uint_as_float(d1b);
            if (d0 < bestd0) { bestd0 = d0; bi0 = v0 + v; }
            if (d1 < bestd1) { bestd1 = d1; bi1 = v0 + v; }
            s0 += ex2f(__uint_as_float(u0b));   // exp(dot), no overflow: dot<=1
            s1 += ex2f(__uint_as_float(u1b));
        }
        __syncthreads();
    }

    int o0 = tok0 * VS + blockIdx.y;
    int o1 = tok1 * VS + blockIdx.y;
    g_pd[o0] = bestd0; g_pi[o0] = bi0; g_ps[o0] = s0;
    g_pd[o1] = bestd1; g_pi[o1] = bi1; g_ps[o1] = s1;
}

// ------------------------- kernel 3: combine + losses + output -------------
__global__ void vq_combine(float* __restrict__ out) {
    int n = blockIdx.x * 128 + threadIdx.x;
    const float* pd = g_pd + n * VS;
    const int*   pi = g_pi + n * VS;
    const float* ps = g_ps + n * VS;

    float bestd = 3.4e38f; int bi = 0; float S = 0.f;
#pragma unroll
    for (int sp = 0; sp < VS; sp++) {
        float d = pd[sp];
        if (d < bestd) { bestd = d; bi = pi[sp]; }  // first-min across ordered splits
        S += ps[sp];
    }
    float lse = lg2f(S) * LN2;

    const float4* ep = (const float4*)(g_en + bi * C_DIM);
    const float4* zp = (const float4*)(g_zfn + n * C_DIM);
    int b = n >> 10, hw = n & 1023;
    float* op = out + b * (C_DIM * 1024) + hw;
    float dot = 0.f, vq = 0.f;
#pragma unroll
    for (int i = 0; i < 8; i++) {
        float4 e = ep[i], zt = zp[i];
        dot = fmaf(e.x, zt.x, fmaf(e.y, zt.y, fmaf(e.z, zt.z, fmaf(e.w, zt.w, dot))));
        float dx = e.x - zt.x, dy = e.y - zt.y, dz = e.z - zt.z, dw = e.w - zt.w;
        vq = fmaf(dx, dx, fmaf(dy, dy, fmaf(dz, dz, fmaf(dw, dw, vq))));
        op[(4 * i + 0) * 1024] = e.x;
        op[(4 * i + 1) * 1024] = e.y;
        op[(4 * i + 2) * 1024] = e.z;
        op[(4 * i + 3) * 1024] = e.w;
    }
    float commit = lse - dot;

    // block reduce: 4 warps
    __shared__ float sred[8];
    float v1 = vq, c1 = commit;
#pragma unroll
    for (int o = 16; o; o >>= 1) {
        v1 += __shfl_down_sync(~0u, v1, o);
        c1 += __shfl_down_sync(~0u, c1, o);
    }
    int wid = threadIdx.x >> 5, lid = threadIdx.x & 31;
    if (lid == 0) { sred[wid] = v1; sred[wid + 4] = c1; }
    __syncthreads();
    if (threadIdx.x == 0) {
        float vsum = sred[0] + sred[1] + sred[2] + sred[3];
        float csum = sred[4] + sred[5] + sred[6] + sred[7];
        g_blk[blockIdx.x][0] = vsum;
        g_blk[blockIdx.x][1] = csum;
        __threadfence();
        int t = atomicAdd(&g_cnt, 1);
        if (t == 63) {                       // last block finalizes
            float va = 0.f, ca = 0.f;
            for (int i = 0; i < 64; i++) { va += g_blk[i][0]; ca += g_blk[i][1]; }
            out[N_TOK * C_DIM]     = va / (float)(N_TOK * C_DIM);   // vq_loss
            out[N_TOK * C_DIM + 1] = 0.25f * (ca / (float)N_TOK);   // commit_loss
            g_cnt = 0;                       // reset for graph replay
        }
    }
}

// ---------------------------------------------------------------------------
extern "C" void kernel_launch(void* const* d_in, const int* in_sizes, int n_in,
                              void* d_out, int out_size) {
    const float* z = (const float*)d_in[0];
    const float* emb = (const float*)d_in[1];
    if (n_in >= 2 && in_sizes[0] == V_CODES * C_DIM && in_sizes[1] == N_TOK * 8) {
        const float* t = z; z = emb; emb = t;
    }
    prep<<<64, 256>>>(z, emb);
    dim3 grid(N_TOK / TOKB, VS);
    vq_main<<<grid, TPB>>>();
    vq_combine<<<N_TOK / 128, 128>>>((float*)d_out);
    (void)out_size;
}